// round 6
// baseline (speedup 1.0000x reference)
#include <cuda_runtime.h>
#include <cstdint>

#define B_ 32
#define C_ 256
#define H_ 32
#define W_ 32
#define K_ 1024
#define N_ 1024
#define I_ 256
#define ZELEMS (B_*C_*H_*W_)   /* 8388608 */
#define NPOS   (B_*N_)         /* 32768   */

#define SZ_Z   15.875f                 /* 127/8  */
#define SE_E   130048.0f               /* 127*1024 */
#define INVSC  (1.0f/(15.875f*130048.0f))
#define EPS_CAND 0.012f
#define CMAX 8

// ---------------- scratch ----------------
__device__ float  g_zz[B_][I_][N_];     // 32 MB exact reinterpreted view [b][i][n]
__device__ int    g_z8p[B_*N_][64];     // 8 MB int8-packed z, [bn][i4]
__device__ int    g_e8p[K_][64];        // 256 KB int8-packed emb
__device__ float  g_t[NPOS];
__device__ float  g_s[K_];
__device__ float          g_cd[NPOS*8*CMAX];
__device__ unsigned short g_ck[NPOS*8*CMAX];
__device__ int            g_ccnt[NPOS*8];
__device__ int    g_idx[NPOS];
__device__ double g_lacc;

__global__ void k_init() { g_lacc = 0.0; }

__device__ __forceinline__ int q8(float v, float sc) {
    int r = __float2int_rn(v * sc);
    return r < -127 ? -127 : (r > 127 ? 127 : r);
}
__device__ __forceinline__ int dp4a(int a, int b, int c) {
    int d;
    asm("dp4a.s32.s32 %0, %1, %2, %3;" : "=r"(d) : "r"(a), "r"(b), "r"(c));
    return d;
}

// ---------------- transpose: z -> g_zz (exact fp32) + g_z8p (int8 packed) ----------------
// zz[b,i,n] = z[b, n&255, i>>3, 4*(i&7)+(n>>8)]
__global__ __launch_bounds__(256) void k_transpose(const float* __restrict__ z) {
    __shared__ float tile[64][33];
    int c0 = blockIdx.x * 64;
    int h  = blockIdx.y;
    int b  = blockIdx.z;
    int t  = threadIdx.x;
    for (int e = t; e < 2048; e += 256) {
        int row = e >> 5, w = e & 31;
        tile[row][w] = z[(((b*C_) + c0 + row)*H_ + h)*W_ + w];
    }
    __syncthreads();
    for (int e = t; e < 2048; e += 256) {
        int cc = e & 63, chunk = e >> 6;
        int il = chunk >> 2, q = chunk & 3;
        g_zz[b][h*8 + il][q*256 + c0 + cc] = tile[cc][il*4 + q];
    }
    // int8 pack: n = q*256+c0+c, i = h*8+il -> words i4 = h*2, h*2+1
    {
        int c = t >> 2, q = t & 3;
        int w0 = 0, w1 = 0;
        #pragma unroll
        for (int il = 0; il < 4; ++il) {
            int v = q8(tile[c][il*4 + q], SZ_Z);
            w0 |= (v & 0xFF) << (il*8);
        }
        #pragma unroll
        for (int il = 4; il < 8; ++il) {
            int v = q8(tile[c][il*4 + q], SZ_Z);
            w1 |= (v & 0xFF) << ((il-4)*8);
        }
        int n = q*256 + c0 + c;
        *(int2*)&g_z8p[(b << 10) + n][h*2] = make_int2(w0, w1);
    }
}

__global__ __launch_bounds__(256) void k_e8(const float* __restrict__ emb) {
    int gid = blockIdx.x*256 + threadIdx.x;      // word id: k*64 + i4
    int k = gid >> 6, i4 = gid & 63;
    float4 e4 = *(const float4*)&emb[k*256 + i4*4];
    int w = (q8(e4.x, SE_E) & 0xFF)
          | ((q8(e4.y, SE_E) & 0xFF) << 8)
          | ((q8(e4.z, SE_E) & 0xFF) << 16)
          | ((q8(e4.w, SE_E) & 0xFF) << 24);
    g_e8p[k][i4] = w;
}

__global__ __launch_bounds__(256) void k_tn() {
    int gn = blockIdx.x*blockDim.x + threadIdx.x;
    if (gn >= NPOS) return;
    int b = gn >> 10, n = gn & 1023;
    float acc = 0.f;
    for (int i = 0; i < I_; ++i) {
        float v = g_zz[b][i][n];
        acc = __fadd_rn(acc, __fmul_rn(v, v));
    }
    g_t[gn] = acc;
}

__global__ __launch_bounds__(256) void k_sk(const float* __restrict__ emb) {
    __shared__ float sm[64*257];
    int k0 = blockIdx.x*64;
    int t = threadIdx.x;
    for (int j = 0; j < 64; ++j)
        sm[j*257 + t] = emb[(k0+j)*256 + t];
    __syncthreads();
    if (t < 64) {
        float acc = 0.f;
        for (int c = 0; c < 256; ++c) {
            float v = sm[t*257 + c];
            acc = __fadd_rn(acc, __fmul_rn(v, v));
        }
        g_s[k0 + t] = acc;
    }
}

// ---------------- DP4A int8 screen GEMM + candidate collection ----------------
// grid (nb=8, kb=8, b=32), 256 thr. Tile 128k x 128n x 256i (64 packed words).
#define SPITCH 132
#define SMW    (64*SPITCH)            /* words per panel: 8448 */
#define SM_TOT (2*SMW*4)              /* 67584 B */

__global__ __launch_bounds__(256, 2) void k_screen() {
    extern __shared__ int smw[];
    int* As = smw;                    // As[i4*SPITCH + k]
    int* Bs = smw + SMW;              // Bs[i4*SPITCH + n]
    int nb = blockIdx.x, kb = blockIdx.y, b = blockIdx.z;
    int n0 = nb*128, k0 = kb*128;
    int t = threadIdx.x;
    int tx = t & 15, ty = t >> 4;

    #pragma unroll
    for (int j = 0; j < 32; ++j) {
        int e = j*256 + t;            // 8192 words
        int r = e >> 6, i4 = e & 63;
        As[i4*SPITCH + r] = g_e8p[k0 + r][i4];
        Bs[i4*SPITCH + r] = g_z8p[(b << 10) + n0 + r][i4];
    }
    __syncthreads();

    int acc[8][8];
    #pragma unroll
    for (int r = 0; r < 8; ++r)
        #pragma unroll
        for (int c = 0; c < 8; ++c) acc[r][c] = 0;

    #pragma unroll 4
    for (int i4 = 0; i4 < 64; ++i4) {
        int a[8], bw[8];
        *(int4*)&a[0]  = *(const int4*)&As[i4*SPITCH + ty*8];
        *(int4*)&a[4]  = *(const int4*)&As[i4*SPITCH + ty*8 + 4];
        *(int4*)&bw[0] = *(const int4*)&Bs[i4*SPITCH + tx*8];
        *(int4*)&bw[4] = *(const int4*)&Bs[i4*SPITCH + tx*8 + 4];
        #pragma unroll
        for (int r = 0; r < 8; ++r)
            #pragma unroll
            for (int c = 0; c < 8; ++c)
                acc[r][c] = dp4a(a[r], bw[c], acc[r][c]);
    }
    __syncthreads();

    // stage screened dists D[k][n]
    float* D = (float*)smw;
    float sv[8], tv[8];
    #pragma unroll
    for (int r = 0; r < 8; ++r) sv[r] = g_s[k0 + ty*8 + r];
    #pragma unroll
    for (int c = 0; c < 8; ++c) tv[c] = g_t[b*1024 + n0 + tx*8 + c];
    #pragma unroll
    for (int r = 0; r < 8; ++r)
        #pragma unroll
        for (int c = 0; c < 8; ++c) {
            float dot = __int2float_rn(acc[r][c]) * INVSC;
            D[(ty*8 + r)*SPITCH + tx*8 + c] = sv[r] + tv[c] - 2.0f*dot;
        }
    __syncthreads();

    // per-position tile min + candidates within EPS of tile min
    if (t < 128) {
        int gn = b*1024 + n0 + t;
        float mn = __int_as_float(0x7f800000);
        for (int k = 0; k < 128; ++k)
            mn = fminf(mn, D[k*SPITCH + t]);
        float thr = mn + EPS_CAND;
        int cnt = 0;
        float cd[CMAX]; unsigned short ck[CMAX];
        for (int k = 0; k < 128; ++k) {
            float d = D[k*SPITCH + t];
            if (d <= thr) {
                if (cnt < CMAX) { cd[cnt] = d; ck[cnt] = (unsigned short)(k0 + k); }
                cnt++;
            }
        }
        int slot = gn*8 + kb;
        g_ccnt[slot] = cnt;
        int nw = cnt < CMAX ? cnt : CMAX;
        for (int c = 0; c < nw; ++c) {
            g_cd[slot*CMAX + c] = cd[c];
            g_ck[slot*CMAX + c] = ck[c];
        }
    }
}

// ---------------- exact recheck (bitwise round-1 selection chain) ----------------
__global__ __launch_bounds__(128) void k_recheck(const float* __restrict__ emb,
                                                 float* __restrict__ out, int out_size) {
    int gn = blockIdx.x*128 + threadIdx.x;
    int b = gn >> 10, n = gn & 1023;
    float tn = g_t[gn];

    float cd[8*CMAX]; unsigned short ck[8*CMAX];
    int total = 0;
    bool ovf = false;
    for (int kb = 0; kb < 8; ++kb) {
        int slot = gn*8 + kb;
        int c = g_ccnt[slot];
        if (c > CMAX) { ovf = true; continue; }
        for (int j = 0; j < c; ++j) {
            cd[total] = g_cd[slot*CMAX + j];
            ck[total] = g_ck[slot*CMAX + j];
            total++;
        }
    }

    float best = __int_as_float(0x7f800000);
    int bi = 0x7fffffff;
    if (!ovf) {
        float gmin = __int_as_float(0x7f800000);
        for (int c = 0; c < total; ++c) gmin = fminf(gmin, cd[c]);
        float thr = gmin + EPS_CAND;
        for (int c = 0; c < total; ++c) {
            if (cd[c] > thr) continue;
            int k = ck[c];
            const float* e = emb + k*256;
            float acc = 0.f;
            for (int i = 0; i < I_; ++i)
                acc = fmaf(e[i], g_zz[b][i][n], acc);
            float d = __fsub_rn(__fadd_rn(g_s[k], tn), __fmul_rn(2.0f, acc));
            if (d < best || (d == best && k < bi)) { best = d; bi = k; }
        }
    } else {
        for (int k = 0; k < K_; ++k) {
            const float* e = emb + k*256;
            float acc = 0.f;
            for (int i = 0; i < I_; ++i)
                acc = fmaf(e[i], g_zz[b][i][n], acc);
            float d = __fsub_rn(__fadd_rn(g_s[k], tn), __fmul_rn(2.0f, acc));
            if (d < best) { best = d; bi = k; }
        }
    }
    g_idx[gn] = bi;
    if (out_size >= ZELEMS + NPOS)      out[ZELEMS + gn] = (float)bi;
    else if (out_size == NPOS)          out[gn]          = (float)bi;
}

// ---------------- writeout + loss ----------------
__global__ __launch_bounds__(256) void k_writeout(const float* __restrict__ z,
                                                  const float* __restrict__ emb,
                                                  float* __restrict__ out, int out_size) {
    int o4 = blockIdx.x*256 + threadIdx.x;
    double local = 0.0;
    if (o4*4 < ZELEMS) {
        int o = o4*4;
        int w = o & 31, h = (o >> 5) & 31, c = (o >> 10) & 255, b = o >> 18;
        float4 zp4 = *(const float4*)&z[o];
        float r[4];
        float zp[4] = {zp4.x, zp4.y, zp4.z, zp4.w};
        #pragma unroll
        for (int j = 0; j < 4; ++j) {
            int n = h*32 + (w + j);
            int kidx = g_idx[b*1024 + n];
            float zq = emb[kidx*256 + c];
            float diff = __fsub_rn(zq, zp[j]);
            r[j] = __fadd_rn(zp[j], diff);
            float sq = __fmul_rn(diff, diff);
            local += (double)sq;
        }
        if (out_size >= ZELEMS) *(float4*)&out[o] = make_float4(r[0], r[1], r[2], r[3]);
    }
    __shared__ double sd[256];
    sd[threadIdx.x] = local;
    __syncthreads();
    for (int s = 128; s > 0; s >>= 1) {
        if (threadIdx.x < s) sd[threadIdx.x] += sd[threadIdx.x + s];
        __syncthreads();
    }
    if (threadIdx.x == 0) atomicAdd(&g_lacc, sd[0]);
}

__global__ void k_finalize(float* __restrict__ out, int out_size) {
    float m = (float)(g_lacc / (double)ZELEMS);
    float loss = __fadd_rn(m, __fmul_rn(0.25f, m));
    if (out_size >= ZELEMS + NPOS + 1)  out[ZELEMS + NPOS] = loss;
    else if (out_size == ZELEMS + 1)    out[ZELEMS]        = loss;
    else if (out_size == 1)             out[0]             = loss;
}

extern "C" void kernel_launch(void* const* d_in, const int* in_sizes, int n_in,
                              void* d_out, int out_size) {
    const float* z   = (const float*)d_in[0];
    const float* emb = (const float*)d_in[1];
    if (n_in >= 2 && in_sizes[0] == K_*C_ && in_sizes[1] == ZELEMS) {
        z = (const float*)d_in[1]; emb = (const float*)d_in[0];
    }
    float* out = (float*)d_out;

    cudaFuncSetAttribute(k_screen, cudaFuncAttributeMaxDynamicSharedMemorySize, SM_TOT);

    k_init<<<1, 1>>>();
    k_transpose<<<dim3(4, 32, 32), 256>>>(z);
    k_e8<<<K_*64/256, 256>>>(emb);
    k_tn<<<NPOS/256, 256>>>();
    k_sk<<<K_/64, 256>>>(emb);
    k_screen<<<dim3(8, 8, 32), 256, SM_TOT>>>();
    k_recheck<<<NPOS/128, 128>>>(emb, out, out_size);
    k_writeout<<<ZELEMS/4/256, 256>>>(z, emb, out, out_size);
    k_finalize<<<1, 1>>>(out, out_size);
}

// round 8
// speedup vs baseline: 1.0340x; 1.0340x over previous
#include <cuda_runtime.h>
#include <cuda_fp16.h>
#include <cstdint>

#define B_ 32
#define C_ 256
#define H_ 32
#define W_ 32
#define K_ 1024
#define N_ 1024
#define I_ 256
#define ZELEMS (B_*C_*H_*W_)   /* 8388608 */
#define NPOS   (B_*N_)         /* 32768   */

#define EPS_CAND 0.02f
#define CMAX 8

// ---------------- scratch ----------------
__device__ float  g_zz[B_][I_][N_];     // 32 MB exact reinterpreted view [b][i][n]
__device__ __half2 g_zh[B_][I_][N_/2];  // 16 MB fp16 z pairs over adjacent n
__device__ __half2 g_ehd[I_][K_];       // 1 MB duplicated fp16 emb: {e,e}
__device__ float  g_t[NPOS];
__device__ float  g_s[K_];
__device__ float          g_cd[NPOS*8*CMAX];
__device__ unsigned short g_ck[NPOS*8*CMAX];
__device__ int            g_ccnt[NPOS*8];
__device__ int    g_idx[NPOS];
__device__ double g_lacc;

__global__ void k_init() { g_lacc = 0.0; }

// ---------------- transpose: z -> g_zz (exact fp32) + g_zh (fp16 n-pairs) ----------------
// zz[b,i,n] = z[b, n&255, i>>3, 4*(i&7)+(n>>8)]
__global__ __launch_bounds__(256) void k_transpose(const float* __restrict__ z) {
    __shared__ float tile[64][33];
    int c0 = blockIdx.x * 64;
    int h  = blockIdx.y;
    int b  = blockIdx.z;
    int t  = threadIdx.x;
    for (int e = t; e < 2048; e += 256) {
        int row = e >> 5, w = e & 31;
        tile[row][w] = z[(((b*C_) + c0 + row)*H_ + h)*W_ + w];
    }
    __syncthreads();
    for (int e = t; e < 2048; e += 256) {
        int cc = e & 63, chunk = e >> 6;
        int il = chunk >> 2, q = chunk & 3;
        g_zz[b][h*8 + il][q*256 + c0 + cc] = tile[cc][il*4 + q];
    }
    // fp16 pack: n-pair (c, c+1) at fixed q; i = h*8 + il
    for (int e = t; e < 1024; e += 256) {
        int c2 = e >> 5, wq = e & 31;
        int il = wq >> 2, q = wq & 3;
        int c = c2*2;
        float v0 = tile[c][il*4 + q];
        float v1 = tile[c+1][il*4 + q];
        int n = q*256 + c0 + c;
        g_zh[b][h*8 + il][n >> 1] = __floats2half2_rn(v0, v1);
    }
}

// duplicated fp16 embedding: g_ehd[i][k] = {e[k][i], e[k][i]}
__global__ __launch_bounds__(256) void k_eh(const float* __restrict__ emb) {
    int gid = blockIdx.x*256 + threadIdx.x;   // i*1024 + k (writes coalesced, reads L2-hot)
    int i = gid >> 10, k = gid & 1023;
    float v = emb[k*256 + i];
    g_ehd[i][k] = __floats2half2_rn(v, v);
}

__global__ __launch_bounds__(256) void k_tn() {
    int gn = blockIdx.x*blockDim.x + threadIdx.x;
    if (gn >= NPOS) return;
    int b = gn >> 10, n = gn & 1023;
    float acc = 0.f;
    for (int i = 0; i < I_; ++i) {
        float v = g_zz[b][i][n];
        acc = __fadd_rn(acc, __fmul_rn(v, v));
    }
    g_t[gn] = acc;
}

__global__ __launch_bounds__(256) void k_sk(const float* __restrict__ emb) {
    __shared__ float sm[64*257];
    int k0 = blockIdx.x*64;
    int t = threadIdx.x;
    for (int j = 0; j < 64; ++j)
        sm[j*257 + t] = emb[(k0+j)*256 + t];
    __syncthreads();
    if (t < 64) {
        float acc = 0.f;
        for (int c = 0; c < 256; ++c) {
            float v = sm[t*257 + c];
            acc = __fadd_rn(acc, __fmul_rn(v, v));
        }
        g_s[k0 + t] = acc;
    }
}

// ---------------- HFMA2 fp16 screen GEMM + candidate collection ----------------
// grid (nb=8, kb=8, b=32), 256 thr. Tile 128k x 128n x 256i, 8 panels of 32 i.
// Es[ii][k]: 128 dup'd half2 (512B row). Zs[ii][n2]: 64 half2 (256B row).
#define EPITCH 128                     /* words per Es row */
#define ZPITCH 64                      /* words per Zs row */
#define SM_ZOFF (32*EPITCH*4)          /* 16 KB */
#define SPITCH 132
#define SM_TOT (128*SPITCH*4)          /* 67584 B: D staging dominates */

__global__ __launch_bounds__(256, 2) void k_screen() {
    extern __shared__ char smraw[];
    unsigned int* Es = (unsigned int*)smraw;
    unsigned int* Zs = (unsigned int*)(smraw + SM_ZOFF);
    float* D = (float*)smraw;          // reused after compute
    int nb = blockIdx.x, kb = blockIdx.y, b = blockIdx.z;
    int n0 = nb*128, k0 = kb*128;
    int t = threadIdx.x;
    int tx = t & 15, ty = t >> 4;

    __half2 acc[8][4];
    #pragma unroll
    for (int r = 0; r < 8; ++r)
        #pragma unroll
        for (int c = 0; c < 4; ++c) acc[r][c] = __floats2half2_rn(0.f, 0.f);

    for (int it = 0; it < 8; ++it) {
        __syncthreads();
        // stage Es: 32 rows x 128 words (straight row copy from g_ehd)
        #pragma unroll
        for (int j = 0; j < 4; ++j) {
            int e = j*256 + t;                   // uint4 id, 32 per row
            int ii = e >> 5, u4 = e & 31;
            ((uint4*)(Es + ii*EPITCH))[u4] =
                ((const uint4*)&g_ehd[it*32 + ii][k0])[u4];
        }
        // stage Zs: 32 rows x 64 words
        #pragma unroll
        for (int j = 0; j < 2; ++j) {
            int e = j*256 + t;                   // uint4 id, 16 per row
            int ii = e >> 4, u4 = e & 15;
            ((uint4*)(Zs + ii*ZPITCH))[u4] =
                ((const uint4*)&g_zh[b][it*32 + ii][nb*64])[u4];
        }
        __syncthreads();
        #pragma unroll
        for (int ii = 0; ii < 32; ++ii) {
            unsigned int a[8], bw[4];
            *(uint4*)&a[0] = *(const uint4*)&Es[ii*EPITCH + ty*8];
            *(uint4*)&a[4] = *(const uint4*)&Es[ii*EPITCH + ty*8 + 4];
            *(uint4*)&bw[0] = *(const uint4*)&Zs[ii*ZPITCH + tx*4];
            #pragma unroll
            for (int r = 0; r < 8; ++r)
                #pragma unroll
                for (int c = 0; c < 4; ++c)
                    acc[r][c] = __hfma2(*(__half2*)&a[r], *(__half2*)&bw[c], acc[r][c]);
        }
    }
    __syncthreads();

    // stage screened dists D[k][n]
    float sv[8], tv[8];
    #pragma unroll
    for (int r = 0; r < 8; ++r) sv[r] = g_s[k0 + ty*8 + r];
    #pragma unroll
    for (int c = 0; c < 8; ++c) tv[c] = g_t[b*1024 + n0 + tx*8 + c];
    #pragma unroll
    for (int r = 0; r < 8; ++r)
        #pragma unroll
        for (int c = 0; c < 4; ++c) {
            float2 d2 = __half22float2(acc[r][c]);
            D[(ty*8 + r)*SPITCH + tx*8 + 2*c]     = sv[r] + tv[2*c]   - 2.0f*d2.x;
            D[(ty*8 + r)*SPITCH + tx*8 + 2*c + 1] = sv[r] + tv[2*c+1] - 2.0f*d2.y;
        }
    __syncthreads();

    // per-position tile min + candidates within EPS of tile min
    if (t < 128) {
        int gn = b*1024 + n0 + t;
        float mn = __int_as_float(0x7f800000);
        for (int k = 0; k < 128; ++k)
            mn = fminf(mn, D[k*SPITCH + t]);
        float thr = mn + EPS_CAND;
        int cnt = 0;
        float cd[CMAX]; unsigned short ck[CMAX];
        for (int k = 0; k < 128; ++k) {
            float d = D[k*SPITCH + t];
            if (d <= thr) {
                if (cnt < CMAX) { cd[cnt] = d; ck[cnt] = (unsigned short)(k0 + k); }
                cnt++;
            }
        }
        int slot = gn*8 + kb;
        g_ccnt[slot] = cnt;
        int nw = cnt < CMAX ? cnt : CMAX;
        for (int c = 0; c < nw; ++c) {
            g_cd[slot*CMAX + c] = cd[c];
            g_ck[slot*CMAX + c] = ck[c];
        }
    }
}

// ---------------- exact recheck (bitwise round-1 selection chain) ----------------
__global__ __launch_bounds__(128) void k_recheck(const float* __restrict__ emb,
                                                 float* __restrict__ out, int out_size) {
    int gn = blockIdx.x*128 + threadIdx.x;
    int b = gn >> 10, n = gn & 1023;
    float tn = g_t[gn];

    float cd[8*CMAX]; unsigned short ck[8*CMAX];
    int total = 0;
    bool ovf = false;
    for (int kb = 0; kb < 8; ++kb) {
        int slot = gn*8 + kb;
        int c = g_ccnt[slot];
        if (c > CMAX) { ovf = true; continue; }
        for (int j = 0; j < c; ++j) {
            cd[total] = g_cd[slot*CMAX + j];
            ck[total] = g_ck[slot*CMAX + j];
            total++;
        }
    }

    float best = __int_as_float(0x7f800000);
    int bi = 0x7fffffff;
    if (!ovf) {
        float gmin = __int_as_float(0x7f800000);
        for (int c = 0; c < total; ++c) gmin = fminf(gmin, cd[c]);
        float thr = gmin + EPS_CAND;
        for (int c = 0; c < total; ++c) {
            if (cd[c] > thr) continue;
            int k = ck[c];
            const float* e = emb + k*256;
            float acc = 0.f;
            for (int i = 0; i < I_; ++i)
                acc = fmaf(e[i], g_zz[b][i][n], acc);
            float d = __fsub_rn(__fadd_rn(g_s[k], tn), __fmul_rn(2.0f, acc));
            if (d < best || (d == best && k < bi)) { best = d; bi = k; }
        }
    } else {
        for (int k = 0; k < K_; ++k) {
            const float* e = emb + k*256;
            float acc = 0.f;
            for (int i = 0; i < I_; ++i)
                acc = fmaf(e[i], g_zz[b][i][n], acc);
            float d = __fsub_rn(__fadd_rn(g_s[k], tn), __fmul_rn(2.0f, acc));
            if (d < best) { best = d; bi = k; }
        }
    }
    g_idx[gn] = bi;
    if (out_size >= ZELEMS + NPOS)      out[ZELEMS + gn] = (float)bi;
    else if (out_size == NPOS)          out[gn]          = (float)bi;
}

// ---------------- writeout + loss ----------------
__global__ __launch_bounds__(256) void k_writeout(const float* __restrict__ z,
                                                  const float* __restrict__ emb,
                                                  float* __restrict__ out, int out_size) {
    int o4 = blockIdx.x*256 + threadIdx.x;
    double local = 0.0;
    if (o4*4 < ZELEMS) {
        int o = o4*4;
        int w = o & 31, h = (o >> 5) & 31, c = (o >> 10) & 255, b = o >> 18;
        float4 zp4 = *(const float4*)&z[o];
        float r[4];
        float zp[4] = {zp4.x, zp4.y, zp4.z, zp4.w};
        #pragma unroll
        for (int j = 0; j < 4; ++j) {
            int n = h*32 + (w + j);
            int kidx = g_idx[b*1024 + n];
            float zq = emb[kidx*256 + c];
            float diff = __fsub_rn(zq, zp[j]);
            r[j] = __fadd_rn(zp[j], diff);
            float sq = __fmul_rn(diff, diff);
            local += (double)sq;
        }
        if (out_size >= ZELEMS) *(float4*)&out[o] = make_float4(r[0], r[1], r[2], r[3]);
    }
    __shared__ double sd[256];
    sd[threadIdx.x] = local;
    __syncthreads();
    for (int s = 128; s > 0; s >>= 1) {
        if (threadIdx.x < s) sd[threadIdx.x] += sd[threadIdx.x + s];
        __syncthreads();
    }
    if (threadIdx.x == 0) atomicAdd(&g_lacc, sd[0]);
}

__global__ void k_finalize(float* __restrict__ out, int out_size) {
    float m = (float)(g_lacc / (double)ZELEMS);
    float loss = __fadd_rn(m, __fmul_rn(0.25f, m));
    if (out_size >= ZELEMS + NPOS + 1)  out[ZELEMS + NPOS] = loss;
    else if (out_size == ZELEMS + 1)    out[ZELEMS]        = loss;
    else if (out_size == 1)             out[0]             = loss;
}

extern "C" void kernel_launch(void* const* d_in, const int* in_sizes, int n_in,
                              void* d_out, int out_size) {
    const float* z   = (const float*)d_in[0];
    const float* emb = (const float*)d_in[1];
    if (n_in >= 2 && in_sizes[0] == K_*C_ && in_sizes[1] == ZELEMS) {
        z = (const float*)d_in[1]; emb = (const float*)d_in[0];
    }
    float* out = (float*)d_out;

    cudaFuncSetAttribute(k_screen, cudaFuncAttributeMaxDynamicSharedMemorySize, SM_TOT);

    k_init<<<1, 1>>>();
    k_transpose<<<dim3(4, 32, 32), 256>>>(z);
    k_eh<<<I_*K_/256, 256>>>(emb);
    k_tn<<<NPOS/256, 256>>>();
    k_sk<<<K_/64, 256>>>(emb);
    k_screen<<<dim3(8, 8, 32), 256, SM_TOT>>>();
    k_recheck<<<NPOS/128, 128>>>(emb, out, out_size);
    k_writeout<<<ZELEMS/4/256, 256>>>(z, emb, out, out_size);
    k_finalize<<<1, 1>>>(out, out_size);
}

// round 14
// speedup vs baseline: 12.6231x; 12.2084x over previous
#include <cuda_runtime.h>
#include <cuda_fp16.h>
#include <cstdint>

#define B_ 32
#define C_ 256
#define H_ 32
#define W_ 32
#define K_ 1024
#define N_ 1024
#define I_ 256
#define ZELEMS (B_*C_*H_*W_)   /* 8388608 */
#define NPOS   (B_*N_)         /* 32768   */

#define EPS_CAND 0.004f
#define CMAX 16

// ---------------- scratch ----------------
__device__ float  g_zz[B_][I_][N_];     // 32 MB exact reinterpreted view [b][i][n]
__device__ __half2 g_zh[B_][I_][N_/2];  // 16 MB fp16 z pairs over adjacent n
__device__ __half2 g_ehd[I_][K_];       // 1 MB duplicated fp16 emb: {e,e}
__device__ float  g_t[NPOS];
__device__ float  g_s[K_];
__device__ float          g_cd[NPOS*8*CMAX];
__device__ unsigned short g_ck[NPOS*8*CMAX];
__device__ int            g_ccnt[NPOS*8];
__device__ int    g_idx[NPOS];
__device__ double g_lacc;

__global__ void k_init() { g_lacc = 0.0; }

// ---------------- transpose: z -> g_zz (exact fp32) + g_zh (fp16 n-pairs) ----------------
// zz[b,i,n] = z[b, n&255, i>>3, 4*(i&7)+(n>>8)]
__global__ __launch_bounds__(256) void k_transpose(const float* __restrict__ z) {
    __shared__ float tile[64][33];
    int c0 = blockIdx.x * 64;
    int h  = blockIdx.y;
    int b  = blockIdx.z;
    int t  = threadIdx.x;
    for (int e = t; e < 2048; e += 256) {
        int row = e >> 5, w = e & 31;
        tile[row][w] = z[(((b*C_) + c0 + row)*H_ + h)*W_ + w];
    }
    __syncthreads();
    for (int e = t; e < 2048; e += 256) {
        int cc = e & 63, chunk = e >> 6;
        int il = chunk >> 2, q = chunk & 3;
        g_zz[b][h*8 + il][q*256 + c0 + cc] = tile[cc][il*4 + q];
    }
    // fp16 pack: n-pair (c, c+1) at fixed q; i = h*8 + il
    for (int e = t; e < 1024; e += 256) {
        int c2 = e >> 5, wq = e & 31;
        int il = wq >> 2, q = wq & 3;
        int c = c2*2;
        float v0 = tile[c][il*4 + q];
        float v1 = tile[c+1][il*4 + q];
        int n = q*256 + c0 + c;
        g_zh[b][h*8 + il][n >> 1] = __floats2half2_rn(v0, v1);
    }
}

// duplicated fp16 embedding: g_ehd[i][k] = {e[k][i], e[k][i]}
__global__ __launch_bounds__(256) void k_eh(const float* __restrict__ emb) {
    int gid = blockIdx.x*256 + threadIdx.x;
    int i = gid >> 10, k = gid & 1023;
    float v = emb[k*256 + i];
    g_ehd[i][k] = __floats2half2_rn(v, v);
}

__global__ __launch_bounds__(256) void k_tn() {
    int gn = blockIdx.x*blockDim.x + threadIdx.x;
    if (gn >= NPOS) return;
    int b = gn >> 10, n = gn & 1023;
    float acc = 0.f;
    for (int i = 0; i < I_; ++i) {
        float v = g_zz[b][i][n];
        acc = __fadd_rn(acc, __fmul_rn(v, v));
    }
    g_t[gn] = acc;
}

__global__ __launch_bounds__(256) void k_sk(const float* __restrict__ emb) {
    __shared__ float sm[64*257];
    int k0 = blockIdx.x*64;
    int t = threadIdx.x;
    for (int j = 0; j < 64; ++j)
        sm[j*257 + t] = emb[(k0+j)*256 + t];
    __syncthreads();
    if (t < 64) {
        float acc = 0.f;
        for (int c = 0; c < 256; ++c) {
            float v = sm[t*257 + c];
            acc = __fadd_rn(acc, __fmul_rn(v, v));
        }
        g_s[k0 + t] = acc;
    }
}

// ---------------- HFMA2 fp16 screen GEMM + candidate collection ----------------
// grid (nb=8, kb=8, b=32), 256 thr. Tile 128k x 128n x 256i, 8 panels of 32 i.
#define EPITCH 128                     /* words per Es row */
#define ZPITCH 64                      /* words per Zs row */
#define SM_ZOFF (32*EPITCH*4)          /* 16 KB */
#define SPITCH 132
#define SM_TOT (128*SPITCH*4)          /* 67584 B: D staging dominates */

__global__ __launch_bounds__(256, 2) void k_screen() {
    extern __shared__ char smraw[];
    unsigned int* Es = (unsigned int*)smraw;
    unsigned int* Zs = (unsigned int*)(smraw + SM_ZOFF);
    float* D = (float*)smraw;          // reused after compute
    int nb = blockIdx.x, kb = blockIdx.y, b = blockIdx.z;
    int n0 = nb*128, k0 = kb*128;
    int t = threadIdx.x;
    int tx = t & 15, ty = t >> 4;

    __half2 acc[8][4];
    #pragma unroll
    for (int r = 0; r < 8; ++r)
        #pragma unroll
        for (int c = 0; c < 4; ++c) acc[r][c] = __floats2half2_rn(0.f, 0.f);

    for (int it = 0; it < 8; ++it) {
        __syncthreads();
        #pragma unroll
        for (int j = 0; j < 4; ++j) {
            int e = j*256 + t;
            int ii = e >> 5, u4 = e & 31;
            ((uint4*)(Es + ii*EPITCH))[u4] =
                ((const uint4*)&g_ehd[it*32 + ii][k0])[u4];
        }
        #pragma unroll
        for (int j = 0; j < 2; ++j) {
            int e = j*256 + t;
            int ii = e >> 4, u4 = e & 15;
            ((uint4*)(Zs + ii*ZPITCH))[u4] =
                ((const uint4*)&g_zh[b][it*32 + ii][nb*64])[u4];
        }
        __syncthreads();
        #pragma unroll
        for (int ii = 0; ii < 32; ++ii) {
            unsigned int a[8], bw[4];
            *(uint4*)&a[0] = *(const uint4*)&Es[ii*EPITCH + ty*8];
            *(uint4*)&a[4] = *(const uint4*)&Es[ii*EPITCH + ty*8 + 4];
            *(uint4*)&bw[0] = *(const uint4*)&Zs[ii*ZPITCH + tx*4];
            #pragma unroll
            for (int r = 0; r < 8; ++r)
                #pragma unroll
                for (int c = 0; c < 4; ++c)
                    acc[r][c] = __hfma2(*(__half2*)&a[r], *(__half2*)&bw[c], acc[r][c]);
        }
    }
    __syncthreads();

    // stage screened dists D[k][n]
    float sv[8], tv[8];
    #pragma unroll
    for (int r = 0; r < 8; ++r) sv[r] = g_s[k0 + ty*8 + r];
    #pragma unroll
    for (int c = 0; c < 8; ++c) tv[c] = g_t[b*1024 + n0 + tx*8 + c];
    #pragma unroll
    for (int r = 0; r < 8; ++r)
        #pragma unroll
        for (int c = 0; c < 4; ++c) {
            float2 d2 = __half22float2(acc[r][c]);
            D[(ty*8 + r)*SPITCH + tx*8 + 2*c]     = sv[r] + tv[2*c]   - 2.0f*d2.x;
            D[(ty*8 + r)*SPITCH + tx*8 + 2*c + 1] = sv[r] + tv[2*c+1] - 2.0f*d2.y;
        }
    __syncthreads();

    // per-position tile min + candidates within EPS of tile min
    if (t < 128) {
        int gn = b*1024 + n0 + t;
        float mn = __int_as_float(0x7f800000);
        for (int k = 0; k < 128; ++k)
            mn = fminf(mn, D[k*SPITCH + t]);
        float thr = mn + EPS_CAND;
        int cnt = 0;
        float cd[CMAX]; unsigned short ck[CMAX];
        for (int k = 0; k < 128; ++k) {
            float d = D[k*SPITCH + t];
            if (d <= thr) {
                if (cnt < CMAX) { cd[cnt] = d; ck[cnt] = (unsigned short)(k0 + k); }
                cnt++;
            }
        }
        int slot = gn*8 + kb;
        g_ccnt[slot] = cnt;
        int nw = cnt < CMAX ? cnt : CMAX;
        for (int c = 0; c < nw; ++c) {
            g_cd[slot*CMAX + c] = cd[c];
            g_ck[slot*CMAX + c] = ck[c];
        }
    }
}

// ---------------- exact recheck (bitwise round-1 selection chain) ----------------
__global__ __launch_bounds__(128) void k_recheck(const float* __restrict__ emb,
                                                 float* __restrict__ out, int out_size) {
    int gn = blockIdx.x*128 + threadIdx.x;
    int b = gn >> 10, n = gn & 1023;
    float tn = g_t[gn];

    float cd[8*CMAX]; unsigned short ck[8*CMAX];
    int total = 0;
    bool ovf = false;
    for (int kb = 0; kb < 8; ++kb) {
        int slot = gn*8 + kb;
        int c = g_ccnt[slot];
        if (c > CMAX) { ovf = true; continue; }
        for (int j = 0; j < c; ++j) {
            cd[total] = g_cd[slot*CMAX + j];
            ck[total] = g_ck[slot*CMAX + j];
            total++;
        }
    }

    float best = __int_as_float(0x7f800000);
    int bi = 0x7fffffff;
    if (!ovf) {
        float gmin = __int_as_float(0x7f800000);
        for (int c = 0; c < total; ++c) gmin = fminf(gmin, cd[c]);
        float thr = gmin + EPS_CAND;
        for (int c = 0; c < total; ++c) {
            if (cd[c] > thr) continue;
            int k = ck[c];
            const float* e = emb + k*256;
            float acc = 0.f;
            for (int i = 0; i < I_; ++i)
                acc = fmaf(e[i], g_zz[b][i][n], acc);
            float d = __fsub_rn(__fadd_rn(g_s[k], tn), __fmul_rn(2.0f, acc));
            if (d < best || (d == best && k < bi)) { best = d; bi = k; }
        }
    } else {
        for (int k = 0; k < K_; ++k) {
            const float* e = emb + k*256;
            float acc = 0.f;
            for (int i = 0; i < I_; ++i)
                acc = fmaf(e[i], g_zz[b][i][n], acc);
            float d = __fsub_rn(__fadd_rn(g_s[k], tn), __fmul_rn(2.0f, acc));
            if (d < best) { best = d; bi = k; }
        }
    }
    g_idx[gn] = bi;
    if (out_size >= ZELEMS + NPOS)      out[ZELEMS + gn] = (float)bi;
    else if (out_size == NPOS)          out[gn]          = (float)bi;
}

// ---------------- writeout + loss ----------------
__global__ __launch_bounds__(256) void k_writeout(const float* __restrict__ z,
                                                  const float* __restrict__ emb,
                                                  float* __restrict__ out, int out_size) {
    int o4 = blockIdx.x*256 + threadIdx.x;
    double local = 0.0;
    if (o4*4 < ZELEMS) {
        int o = o4*4;
        int w = o & 31, h = (o >> 5) & 31, c = (o >> 10) & 255, b = o >> 18;
        float4 zp4 = *(const float4*)&z[o];
        float r[4];
        float zp[4] = {zp4.x, zp4.y, zp4.z, zp4.w};
        #pragma unroll
        for (int j = 0; j < 4; ++j) {
            int n = h*32 + (w + j);
            int kidx = g_idx[b*1024 + n];
            float zq = emb[kidx*256 + c];
            float diff = __fsub_rn(zq, zp[j]);
            r[j] = __fadd_rn(zp[j], diff);
            float sq = __fmul_rn(diff, diff);
            local += (double)sq;
        }
        if (out_size >= ZELEMS) *(float4*)&out[o] = make_float4(r[0], r[1], r[2], r[3]);
    }
    __shared__ double sd[256];
    sd[threadIdx.x] = local;
    __syncthreads();
    for (int s = 128; s > 0; s >>= 1) {
        if (threadIdx.x < s) sd[threadIdx.x] += sd[threadIdx.x + s];
        __syncthreads();
    }
    if (threadIdx.x == 0) atomicAdd(&g_lacc, sd[0]);
}

__global__ void k_finalize(float* __restrict__ out, int out_size) {
    float m = (float)(g_lacc / (double)ZELEMS);
    float loss = __fadd_rn(m, __fmul_rn(0.25f, m));
    if (out_size >= ZELEMS + NPOS + 1)  out[ZELEMS + NPOS] = loss;
    else if (out_size == ZELEMS + 1)    out[ZELEMS]        = loss;
    else if (out_size == 1)             out[0]             = loss;
}

extern "C" void kernel_launch(void* const* d_in, const int* in_sizes, int n_in,
                              void* d_out, int out_size) {
    const float* z   = (const float*)d_in[0];
    const float* emb = (const float*)d_in[1];
    if (n_in >= 2 && in_sizes[0] == K_*C_ && in_sizes[1] == ZELEMS) {
        z = (const float*)d_in[1]; emb = (const float*)d_in[0];
    }
    float* out = (float*)d_out;

    cudaFuncSetAttribute(k_screen, cudaFuncAttributeMaxDynamicSharedMemorySize, SM_TOT);

    k_init<<<1, 1>>>();
    k_transpose<<<dim3(4, 32, 32), 256>>>(z);
    k_eh<<<I_*K_/256, 256>>>(emb);
    k_tn<<<NPOS/256, 256>>>();
    k_sk<<<K_/64, 256>>>(emb);
    k_screen<<<dim3(8, 8, 32), 256, SM_TOT>>>();
    k_recheck<<<NPOS/128, 128>>>(emb, out, out_size);
    k_writeout<<<ZELEMS/4/256, 256>>>(z, emb, out, out_size);
    k_finalize<<<1, 1>>>(out, out_size);
}